// round 6
// baseline (speedup 1.0000x reference)
#include <cuda_runtime.h>
#include <math.h>
#include <stdint.h>

#define BSZ   4096
#define QSZ   32768
#define DIM   128
#define QSPLIT 8
#define QPART (QSZ / QSPLIT)   // 4096

#define INV_T 10.0f
#define SHIFT 10.0f

// ---------------- scratch (static device globals; no allocation) ----------------
__device__ float g_pn[2][BSZ * DIM];          // normalized p1, p2          (4 MB)
__device__ float g_nn[2][BSZ * DIM];          // gathered nearest neighbors (4 MB)
__device__ float g_pval[2][QSPLIT][BSZ];      // partial argmax values (tf32 path)
__device__ int   g_pidx[2][QSPLIT][BSZ];      // partial argmax indices
__device__ float g_colpart[2][64][BSZ];       // per-rowblock partial column sums (2 MB)
__device__ float g_diag[2][BSZ];              // diagonal logits (=10*dot)

// ---------------- K1: L2 normalize (one warp per row) ----------------
__global__ void k_normalize(const float* __restrict__ p1, const float* __restrict__ p2) {
    int gw   = (blockIdx.x * blockDim.x + threadIdx.x) >> 5;
    int lane = threadIdx.x & 31;
    if (gw >= 2 * BSZ) return;
    int input = gw >> 12;            // /4096
    int row   = gw & (BSZ - 1);
    const float* src = (input ? p2 : p1) + (size_t)row * DIM;
    float4 v = ((const float4*)src)[lane];
    float s = v.x * v.x + v.y * v.y + v.z * v.z + v.w * v.w;
#pragma unroll
    for (int o = 16; o; o >>= 1) s += __shfl_xor_sync(0xffffffff, s, o);
    float inv = rsqrtf(s);
    float4 o4 = make_float4(v.x * inv, v.y * inv, v.z * inv, v.w * inv);
    ((float4*)(g_pn[input] + (size_t)row * DIM))[lane] = o4;
}

// ---------------- K2: 3xTF32 (emulated fp32) mma GEMM + running argmax ----------------
// grid (BSZ/128, 2, QSPLIT), block 256 (8 warps as 4 wm x 2 wn). BM=128, BN=64.
// Warp tile 32x32 = 2 m-atoms x 4 n-atoms of m16n8k8.
// A (128x128 fp32) persistent in smem (stride 132), split big/res on the fly.
// B streamed in 32-k chunks, pre-split into Bbig/Bres smem (stride 36).
// C += Abig*Bbig + Abig*Bres + Ares*Bbig   (res.res dropped, ~2^-22)
#define ASTRIDE 132
#define BSTRIDE 36
#define NN_A_FLOATS (128 * ASTRIDE)            // 16896
#define NN_B_FLOATS (64 * BSTRIDE)             // 2304
#define NN_SMEM_BYTES ((NN_A_FLOATS + 2 * NN_B_FLOATS + 256 + 256) * 4)   // ~88 KB

__device__ __forceinline__ void mma_tf32(float c[4], const uint32_t a[4], const uint32_t b[2]) {
    asm volatile(
        "mma.sync.aligned.m16n8k8.row.col.f32.tf32.tf32.f32 "
        "{%0,%1,%2,%3}, {%4,%5,%6,%7}, {%8,%9}, {%0,%1,%2,%3};\n"
        : "+f"(c[0]), "+f"(c[1]), "+f"(c[2]), "+f"(c[3])
        : "r"(a[0]), "r"(a[1]), "r"(a[2]), "r"(a[3]), "r"(b[0]), "r"(b[1]));
}

__device__ __forceinline__ uint32_t to_tf32_rna(float x) {
    uint32_t r;
    asm("cvt.rna.tf32.f32 %0, %1;" : "=r"(r) : "f"(x));
    return r;
}

__global__ void __launch_bounds__(256, 2) k_nn(const float* __restrict__ queue) {
    extern __shared__ float sm[];
    float* As   = sm;                              // raw fp32 A [128][132]
    float* Bbig = sm + NN_A_FLOATS;                // [64][36]
    float* Bres = Bbig + NN_B_FLOATS;              // [64][36]
    float* sval = Bres + NN_B_FLOATS;              // [128][2]
    int*   sidx = (int*)(sval + 256);              // [128][2]

    const int rb = blockIdx.x, input = blockIdx.y, qseg = blockIdx.z;
    const float* A  = g_pn[input] + (size_t)rb * 128 * DIM;
    const float* Bq = queue + (size_t)qseg * QPART * DIM;
    const int tid = threadIdx.x, lane = tid & 31, wid = tid >> 5;
    const int wm = wid & 3, wn = wid >> 2;         // 4 x 2 warp grid
    const int gId = lane >> 2, tig = lane & 3;

    // load A tile once (raw fp32)
#pragma unroll
    for (int x = 0; x < 16; x++) {
        int f = tid + x * 256;                      // 0..4095 float4 slots
        int row = f >> 5, kq = f & 31;
        float4 v = *(const float4*)(A + (size_t)row * DIM + kq * 4);
        *(float4*)(As + row * ASTRIDE + kq * 4) = v;
    }

    // running best: 4 row-slots = 2 m-atoms x {gId, gId+8}
    float best[4]; int bidx[4];
#pragma unroll
    for (int s = 0; s < 4; s++) { best[s] = -3.4e38f; bidx[s] = 0; }

#pragma unroll 1
    for (int qt = 0; qt < QPART; qt += 64) {
        float c[2][4][4];
#pragma unroll
        for (int ma = 0; ma < 2; ma++)
#pragma unroll
            for (int na = 0; na < 4; na++)
#pragma unroll
                for (int r = 0; r < 4; r++) c[ma][na][r] = 0.f;

#pragma unroll 1
        for (int kk = 0; kk < DIM; kk += 32) {
            __syncthreads();
            // load + split B chunk [64 n][32 k]
#pragma unroll
            for (int x = 0; x < 2; x++) {
                int f = tid + x * 256;              // 0..511 float4 slots
                int row = f >> 3, kq = f & 7;
                float4 v = *(const float4*)(Bq + (size_t)(qt + row) * DIM + kk + kq * 4);
                float4 bg, br;
                bg.x = __uint_as_float(to_tf32_rna(v.x)); br.x = v.x - bg.x;
                bg.y = __uint_as_float(to_tf32_rna(v.y)); br.y = v.y - bg.y;
                bg.z = __uint_as_float(to_tf32_rna(v.z)); br.z = v.z - bg.z;
                bg.w = __uint_as_float(to_tf32_rna(v.w)); br.w = v.w - bg.w;
                *(float4*)(Bbig + row * BSTRIDE + kq * 4) = bg;
                *(float4*)(Bres + row * BSTRIDE + kq * 4) = br;
            }
            __syncthreads();
#pragma unroll
            for (int ka = 0; ka < 4; ka++) {
                int k0 = kk + ka * 8;
                uint32_t afb[2][4], afr[2][4], bfb[4][2], bfr[4][2];
#pragma unroll
                for (int ma = 0; ma < 2; ma++) {
                    int r0 = wm * 32 + ma * 16;
#pragma unroll
                    for (int q = 0; q < 4; q++) {
                        int rr = r0 + gId + ((q & 1) ? 8 : 0);
                        int ck = k0 + tig + ((q & 2) ? 4 : 0);
                        float a = As[rr * ASTRIDE + ck];
                        uint32_t big = to_tf32_rna(a);
                        afb[ma][q] = big;
                        afr[ma][q] = __float_as_uint(a - __uint_as_float(big));
                    }
                }
#pragma unroll
                for (int na = 0; na < 4; na++) {
                    int n0 = wn * 32 + na * 8;
                    int base = (n0 + gId) * BSTRIDE + (k0 - kk) + tig;
                    bfb[na][0] = __float_as_uint(Bbig[base]);
                    bfb[na][1] = __float_as_uint(Bbig[base + 4]);
                    bfr[na][0] = __float_as_uint(Bres[base]);
                    bfr[na][1] = __float_as_uint(Bres[base + 4]);
                }
#pragma unroll
                for (int ma = 0; ma < 2; ma++)
#pragma unroll
                    for (int na = 0; na < 4; na++) {
                        mma_tf32(c[ma][na], afb[ma], bfb[na]);
                        mma_tf32(c[ma][na], afb[ma], bfr[na]);
                        mma_tf32(c[ma][na], afr[ma], bfb[na]);
                    }
            }
        }
        // fold this 64-col tile into the running argmax
        int colb = qseg * QPART + qt + wn * 32;
#pragma unroll
        for (int ma = 0; ma < 2; ma++) {
#pragma unroll
            for (int na = 0; na < 4; na++) {
                int cb = colb + na * 8 + 2 * tig;
                if (c[ma][na][0] > best[ma * 2]) { best[ma * 2] = c[ma][na][0]; bidx[ma * 2] = cb; }
                if (c[ma][na][1] > best[ma * 2]) { best[ma * 2] = c[ma][na][1]; bidx[ma * 2] = cb + 1; }
                if (c[ma][na][2] > best[ma * 2 + 1]) { best[ma * 2 + 1] = c[ma][na][2]; bidx[ma * 2 + 1] = cb; }
                if (c[ma][na][3] > best[ma * 2 + 1]) { best[ma * 2 + 1] = c[ma][na][3]; bidx[ma * 2 + 1] = cb + 1; }
            }
        }
    }

    // reduce across tig lanes (same row), then across the 2 column-warps
    __syncthreads();
#pragma unroll
    for (int s = 0; s < 4; s++) {
        float v = best[s]; int ix = bidx[s];
#pragma unroll
        for (int off = 1; off <= 2; off <<= 1) {
            float ov = __shfl_xor_sync(0xffffffff, v, off);
            int   oi = __shfl_xor_sync(0xffffffff, ix, off);
            if (ov > v || (ov == v && oi < ix)) { v = ov; ix = oi; }
        }
        if (tig == 0) {
            int row = wm * 32 + (s >> 1) * 16 + gId + ((s & 1) ? 8 : 0);
            sval[row * 2 + wn] = v;
            sidx[row * 2 + wn] = ix;
        }
    }
    __syncthreads();
    if (tid < 128) {
        float bv = sval[tid * 2]; int bi = sidx[tid * 2];
        float v2 = sval[tid * 2 + 1]; int i2 = sidx[tid * 2 + 1];
        if (v2 > bv || (v2 == bv && i2 < bi)) { bv = v2; bi = i2; }
        g_pval[input][qseg][rb * 128 + tid] = bv;
        g_pidx[input][qseg][rb * 128 + tid] = bi;
    }
}

// ---------------- K3: EXACT fp32 rescore of segment candidates + gather ----------------
// One warp per row. Recomputes the 8 candidate dots in fp32, picks max with
// first-index tie-break (matches jnp.argmax). Final selection independent of TF32.
__global__ void k_gather(const float* __restrict__ queue) {
    int gw   = (blockIdx.x * blockDim.x + threadIdx.x) >> 5;
    int lane = threadIdx.x & 31;
    if (gw >= 2 * BSZ) return;
    int input = gw >> 12, row = gw & (BSZ - 1);
    float4 p = ((const float4*)(g_pn[input] + (size_t)row * DIM))[lane];
    float bv = -3.4e38f; int bi = 0x7fffffff;
#pragma unroll
    for (int s = 0; s < QSPLIT; s++) {
        int idx = g_pidx[input][s][row];
        float4 q = ((const float4*)(queue + (size_t)idx * DIM))[lane];
        float d = p.x * q.x + p.y * q.y + p.z * q.z + p.w * q.w;
#pragma unroll
        for (int o = 16; o; o >>= 1) d += __shfl_xor_sync(0xffffffff, d, o);
        if (d > bv || (d == bv && idx < bi)) { bv = d; bi = idx; }
    }
    // xor-reduction gives identical sum on all lanes -> all lanes agree on bi
    float4 q = ((const float4*)(queue + (size_t)bi * DIM))[lane];
    ((float4*)(g_nn[input] + (size_t)row * DIM))[lane] = q;
}

// ---------------- K4: logits GEMM (SIMT fp32) + fixed-shift exp row/col sums ----------------
// grid (64, 2), block 128. m=0: M1=n1@p2^T, m=1: M2=n2@p1^T.
#define APAD 68
#define LG_A_FLOATS (DIM * APAD)         // 8704
#define LG_B_FLOATS (32 * 128)           // 4096
#define LG_SCOL     (8 * 128)            // 1024
#define LG_SROW     (64 * 16)            // 1024
#define LG_SMEM_BYTES ((LG_A_FLOATS + LG_B_FLOATS + LG_SCOL + LG_SROW + 64) * 4)

__global__ void __launch_bounds__(128) k_logits(float* __restrict__ out) {
    extern __shared__ float smL[];
    float* As    = smL;                         // [128][APAD]
    float* Bs    = As + LG_A_FLOATS;            // [32][128]
    float* scol  = Bs + LG_B_FLOATS;            // [8][128]
    float* srow  = scol + LG_SCOL;              // [64][16]
    float* sdiag = srow + LG_SROW;              // [64]

    const int rb = blockIdx.x, m = blockIdx.y;
    const float* A  = g_nn[m] + (size_t)rb * 64 * DIM;
    const float* Bm = g_pn[1 - m];
    const int tid = threadIdx.x;
    const int rg = tid >> 4, cg = tid & 15;

#pragma unroll
    for (int x = 0; x < 16; x++) {
        int f = tid + x * 128;
        int row = f >> 5, kq = f & 31;
        float4 v = *(const float4*)(A + (size_t)row * DIM + kq * 4);
        As[(kq * 4 + 0) * APAD + row] = v.x; As[(kq * 4 + 1) * APAD + row] = v.y;
        As[(kq * 4 + 2) * APAD + row] = v.z; As[(kq * 4 + 3) * APAD + row] = v.w;
    }

    float rowsum[8];
#pragma unroll
    for (int i = 0; i < 8; i++) rowsum[i] = 0.f;

#pragma unroll 1
    for (int nt = 0; nt < BSZ; nt += 128) {
        float acc[8][8];
#pragma unroll
        for (int i = 0; i < 8; i++)
#pragma unroll
            for (int j = 0; j < 8; j++) acc[i][j] = 0.f;

#pragma unroll 1
        for (int kk = 0; kk < DIM; kk += 32) {
            __syncthreads();
#pragma unroll
            for (int x = 0; x < 8; x++) {
                int f = tid + x * 128;
                int row = f >> 3, kq = f & 7;
                float4 v = *(const float4*)(Bm + (size_t)(nt + row) * DIM + kk + kq * 4);
                Bs[(kq * 4 + 0) * 128 + row] = v.x; Bs[(kq * 4 + 1) * 128 + row] = v.y;
                Bs[(kq * 4 + 2) * 128 + row] = v.z; Bs[(kq * 4 + 3) * 128 + row] = v.w;
            }
            __syncthreads();
#pragma unroll 8
            for (int k = 0; k < 32; k++) {
                float a[8], b[8];
                *(float4*)(a)     = *(const float4*)(As + (kk + k) * APAD + rg * 8);
                *(float4*)(a + 4) = *(const float4*)(As + (kk + k) * APAD + rg * 8 + 4);
                *(float4*)(b)     = *(const float4*)(Bs + k * 128 + cg * 8);
                *(float4*)(b + 4) = *(const float4*)(Bs + k * 128 + cg * 8 + 4);
#pragma unroll
                for (int i = 0; i < 8; i++)
#pragma unroll
                    for (int j = 0; j < 8; j++)
                        acc[i][j] = fmaf(a[i], b[j], acc[i][j]);
            }
        }
        float colp[8];
#pragma unroll
        for (int j = 0; j < 8; j++) colp[j] = 0.f;
#pragma unroll
        for (int i = 0; i < 8; i++) {
            int grow = rb * 64 + rg * 8 + i;
#pragma unroll
            for (int j = 0; j < 8; j++) {
                float l = acc[i][j] * INV_T;
                float e = __expf(l - SHIFT);
                rowsum[i] += e;
                colp[j]   += e;
                int col = nt + cg * 8 + j;
                if (col == grow) { sdiag[rg * 8 + i] = l; g_diag[m][grow] = l; }
            }
        }
#pragma unroll
        for (int j = 0; j < 8; j++) scol[rg * 128 + cg * 8 + j] = colp[j];
        __syncthreads();
        {
            float cs = 0.f;
#pragma unroll
            for (int r = 0; r < 8; r++) cs += scol[r * 128 + tid];
            g_colpart[m][rb][nt + tid] = cs;
        }
        __syncthreads();
    }
#pragma unroll
    for (int i = 0; i < 8; i++) srow[(rg * 8 + i) * 16 + cg] = rowsum[i];
    __syncthreads();
    if (tid < 64) {
        float s = 0.f;
        for (int c = 0; c < 16; c++) s += srow[tid * 16 + c];
        int grow = rb * 64 + tid;
        out[(size_t)(2 * m) * BSZ + grow] = SHIFT + logf(s) - sdiag[tid];
    }
}

// ---------------- K5: column losses (transposed segments) ----------------
__global__ void k_colloss(float* __restrict__ out) {
    int g = blockIdx.x * blockDim.x + threadIdx.x;
    if (g >= 2 * BSZ) return;
    int m = g >> 12, col = g & (BSZ - 1);
    float s = 0.f;
#pragma unroll 8
    for (int rb = 0; rb < 64; rb++) s += g_colpart[m][rb][col];
    out[(size_t)(2 * m + 1) * BSZ + col] = SHIFT + logf(s) - g_diag[m][col];
}

// ---------------- launch ----------------
extern "C" void kernel_launch(void* const* d_in, const int* in_sizes, int n_in,
                              void* d_out, int out_size) {
    const float *p1 = nullptr, *p2 = nullptr, *queue = nullptr;
    for (int i = 0; i < n_in; i++) {
        if (in_sizes[i] == QSZ * DIM) queue = (const float*)d_in[i];
        else if (!p1) p1 = (const float*)d_in[i];
        else p2 = (const float*)d_in[i];
    }
    float* out = (float*)d_out;

    cudaFuncSetAttribute(k_nn, cudaFuncAttributeMaxDynamicSharedMemorySize, NN_SMEM_BYTES);
    cudaFuncSetAttribute(k_logits, cudaFuncAttributeMaxDynamicSharedMemorySize, LG_SMEM_BYTES);

    k_normalize<<<(2 * BSZ * 32 + 255) / 256, 256>>>(p1, p2);

    dim3 g2(BSZ / 128, 2, QSPLIT);
    k_nn<<<g2, 256, NN_SMEM_BYTES>>>(queue);

    k_gather<<<(2 * BSZ * 32 + 255) / 256, 256>>>(queue);

    dim3 g4(BSZ / 64, 2);
    k_logits<<<g4, 128, LG_SMEM_BYTES>>>(out);

    k_colloss<<<(2 * BSZ + 255) / 256, 256>>>(out);
}

// round 7
// speedup vs baseline: 1.1687x; 1.1687x over previous
#include <cuda_runtime.h>
#include <math.h>
#include <stdint.h>

#define BSZ   4096
#define QSZ   32768
#define DIM   128
#define QSPLIT 8
#define QPART (QSZ / QSPLIT)   // 4096
#define NSEG  4
#define NSEG_COLS (BSZ / NSEG) // 1024

#define INV_T 10.0f
#define SHIFT 10.0f

// ---------------- scratch (static device globals; no allocation) ----------------
__device__ float g_pn[2][BSZ * DIM];          // normalized p1, p2
__device__ float g_nn[2][BSZ * DIM];          // gathered nearest neighbors
__device__ float g_pval[2][QSPLIT][BSZ];      // partial argmax values (tf32 path)
__device__ int   g_pidx[2][QSPLIT][BSZ];      // partial argmax indices
__device__ float g_rowpart[2][NSEG][BSZ];     // per-colsegment partial row sums
__device__ float g_colpart[2][32][BSZ];       // per-rowblock partial col sums
__device__ float g_diag[2][BSZ];              // diagonal logits

__device__ __forceinline__ void mma_tf32(float c[4], const uint32_t a[4], const uint32_t b[2]) {
    asm volatile(
        "mma.sync.aligned.m16n8k8.row.col.f32.tf32.tf32.f32 "
        "{%0,%1,%2,%3}, {%4,%5,%6,%7}, {%8,%9}, {%0,%1,%2,%3};\n"
        : "+f"(c[0]), "+f"(c[1]), "+f"(c[2]), "+f"(c[3])
        : "r"(a[0]), "r"(a[1]), "r"(a[2]), "r"(a[3]), "r"(b[0]), "r"(b[1]));
}
__device__ __forceinline__ uint32_t to_tf32_rna(float x) {
    uint32_t r;
    asm("cvt.rna.tf32.f32 %0, %1;" : "=r"(r) : "f"(x));
    return r;
}

// ---------------- K1: L2 normalize (one warp per row) ----------------
__global__ void k_normalize(const float* __restrict__ p1, const float* __restrict__ p2) {
    int gw   = (blockIdx.x * blockDim.x + threadIdx.x) >> 5;
    int lane = threadIdx.x & 31;
    if (gw >= 2 * BSZ) return;
    int input = gw >> 12;
    int row   = gw & (BSZ - 1);
    const float* src = (input ? p2 : p1) + (size_t)row * DIM;
    float4 v = ((const float4*)src)[lane];
    float s = v.x * v.x + v.y * v.y + v.z * v.z + v.w * v.w;
#pragma unroll
    for (int o = 16; o; o >>= 1) s += __shfl_xor_sync(0xffffffff, s, o);
    float inv = rsqrtf(s);
    float4 o4 = make_float4(v.x * inv, v.y * inv, v.z * inv, v.w * inv);
    ((float4*)(g_pn[input] + (size_t)row * DIM))[lane] = o4;
}

// ---------------- shared macros for the 3xTF32 engine ----------------
#define ASTRIDE 132
#define BSTRIDE 36
#define A_FLOATS (128 * ASTRIDE)               // 16896
#define BBUF_FLOATS (64 * BSTRIDE)             // 2304
#define BREGION_FLOATS (4 * BBUF_FLOATS)       // 9216 (big/res x 2 buffers)

// load chunk ch (64 rows x 32 k) into pv[2]
#define LOADB(Bsrc, rowbase, ch, pv)                                              \
    {                                                                             \
        int _qtn = (rowbase) + ((ch) >> 2) * 64, _kkn = ((ch) & 3) * 32;          \
        _Pragma("unroll")                                                         \
        for (int _x = 0; _x < 2; _x++) {                                          \
            int _f = tid + _x * 256, _row = _f >> 3, _kq = _f & 7;                \
            pv[_x] = *(const float4*)((Bsrc) + (size_t)(_qtn + _row) * DIM + _kkn + _kq * 4); \
        }                                                                         \
    }

// split-store chunk ch from pv[2] into buffer (ch&1)
#define STOREB(Bbase, ch, pv)                                                     \
    {                                                                             \
        float* _bb = (Bbase) + ((ch) & 1) * (2 * BBUF_FLOATS);                    \
        float* _br = _bb + BBUF_FLOATS;                                           \
        _Pragma("unroll")                                                         \
        for (int _x = 0; _x < 2; _x++) {                                          \
            int _f = tid + _x * 256, _row = _f >> 3, _kq = _f & 7;                \
            float4 _v = pv[_x], _bg, _rr;                                         \
            _bg.x = __uint_as_float(to_tf32_rna(_v.x)); _rr.x = _v.x - _bg.x;     \
            _bg.y = __uint_as_float(to_tf32_rna(_v.y)); _rr.y = _v.y - _bg.y;     \
            _bg.z = __uint_as_float(to_tf32_rna(_v.z)); _rr.z = _v.z - _bg.z;     \
            _bg.w = __uint_as_float(to_tf32_rna(_v.w)); _rr.w = _v.w - _bg.w;     \
            *(float4*)(_bb + _row * BSTRIDE + _kq * 4) = _bg;                     \
            *(float4*)(_br + _row * BSTRIDE + _kq * 4) = _rr;                     \
        }                                                                         \
    }

// 3xTF32 mma over one 32-k chunk of buffer (ch&1); accumulates c[2][4][4]
#define MMA_CHUNK(As, Bbase, ch, c)                                               \
    {                                                                             \
        float* _bb = (Bbase) + ((ch) & 1) * (2 * BBUF_FLOATS);                    \
        float* _br = _bb + BBUF_FLOATS;                                           \
        int _kkb = ((ch) & 3) * 32;                                               \
        _Pragma("unroll")                                                         \
        for (int _ka = 0; _ka < 4; _ka++) {                                       \
            int _k0 = _kkb + _ka * 8;                                             \
            uint32_t _afb[2][4], _afr[2][4], _bfb[4][2], _bfr[4][2];              \
            _Pragma("unroll")                                                     \
            for (int _ma = 0; _ma < 2; _ma++) {                                   \
                int _r0 = wm * 32 + _ma * 16;                                     \
                _Pragma("unroll")                                                 \
                for (int _q = 0; _q < 4; _q++) {                                  \
                    int _rr2 = _r0 + gId + ((_q & 1) ? 8 : 0);                    \
                    int _ck = _k0 + tig + ((_q & 2) ? 4 : 0);                     \
                    float _a = (As)[_rr2 * ASTRIDE + _ck];                        \
                    uint32_t _big = to_tf32_rna(_a);                              \
                    _afb[_ma][_q] = _big;                                         \
                    _afr[_ma][_q] = __float_as_uint(_a - __uint_as_float(_big));  \
                }                                                                 \
            }                                                                     \
            _Pragma("unroll")                                                     \
            for (int _na = 0; _na < 4; _na++) {                                   \
                int _base = (wn * 32 + _na * 8 + gId) * BSTRIDE + (_k0 - _kkb) + tig; \
                _bfb[_na][0] = __float_as_uint(_bb[_base]);                       \
                _bfb[_na][1] = __float_as_uint(_bb[_base + 4]);                   \
                _bfr[_na][0] = __float_as_uint(_br[_base]);                       \
                _bfr[_na][1] = __float_as_uint(_br[_base + 4]);                   \
            }                                                                     \
            _Pragma("unroll")                                                     \
            for (int _ma = 0; _ma < 2; _ma++)                                     \
                _Pragma("unroll")                                                 \
                for (int _na = 0; _na < 4; _na++) {                               \
                    mma_tf32(c[_ma][_na], _afb[_ma], _bfb[_na]);                  \
                    mma_tf32(c[_ma][_na], _afb[_ma], _bfr[_na]);                  \
                    mma_tf32(c[_ma][_na], _afr[_ma], _bfb[_na]);                  \
                }                                                                 \
        }                                                                         \
    }

// ---------------- K2: 3xTF32 GEMM + running argmax, double-buffered B ----------------
// grid (32, 2, 8), block 256 (4 wm x 2 wn warps). BM=128, BN=64.
#define NN_SMEM_BYTES ((A_FLOATS + BREGION_FLOATS + 256 + 256) * 4)  // ~104 KB

__global__ void __launch_bounds__(256, 2) k_nn(const float* __restrict__ queue) {
    extern __shared__ float sm[];
    float* As    = sm;
    float* Bbase = sm + A_FLOATS;
    float* sval  = Bbase + BREGION_FLOATS;     // [128][2]
    int*   sidx  = (int*)(sval + 256);

    const int rb = blockIdx.x, input = blockIdx.y, qseg = blockIdx.z;
    const float* A  = g_pn[input] + (size_t)rb * 128 * DIM;
    const float* Bq = queue + (size_t)qseg * QPART * DIM;
    const int tid = threadIdx.x, lane = tid & 31, wid = tid >> 5;
    const int wm = wid & 3, wn = wid >> 2;
    const int gId = lane >> 2, tig = lane & 3;

    // persistent A tile (raw fp32)
#pragma unroll
    for (int x = 0; x < 16; x++) {
        int f = tid + x * 256;
        int row = f >> 5, kq = f & 31;
        float4 v = *(const float4*)(A + (size_t)row * DIM + kq * 4);
        *(float4*)(As + row * ASTRIDE + kq * 4) = v;
    }

    float best[4]; int bidx[4];
#pragma unroll
    for (int s = 0; s < 4; s++) { best[s] = -3.4e38f; bidx[s] = 0; }

    const int NCH = (QPART / 64) * 4;          // 256 chunks
    float4 pv[2];
    LOADB(Bq, 0, 0, pv);
    STOREB(Bbase, 0, pv);
    __syncthreads();

#pragma unroll 1
    for (int qi = 0; qi < QPART / 64; qi++) {
        float c[2][4][4];
#pragma unroll
        for (int ma = 0; ma < 2; ma++)
#pragma unroll
            for (int na = 0; na < 4; na++)
#pragma unroll
                for (int r = 0; r < 4; r++) c[ma][na][r] = 0.f;

#pragma unroll 1
        for (int kk = 0; kk < 4; kk++) {
            int ch = qi * 4 + kk;
            if (ch + 1 < NCH) LOADB(Bq, 0, ch + 1, pv);
            MMA_CHUNK(As, Bbase, ch, c);
            if (ch + 1 < NCH) STOREB(Bbase, ch + 1, pv);
            __syncthreads();
        }

        int colb = qseg * QPART + qi * 64 + wn * 32;
#pragma unroll
        for (int ma = 0; ma < 2; ma++) {
#pragma unroll
            for (int na = 0; na < 4; na++) {
                int cb = colb + na * 8 + 2 * tig;
                if (c[ma][na][0] > best[ma * 2]) { best[ma * 2] = c[ma][na][0]; bidx[ma * 2] = cb; }
                if (c[ma][na][1] > best[ma * 2]) { best[ma * 2] = c[ma][na][1]; bidx[ma * 2] = cb + 1; }
                if (c[ma][na][2] > best[ma * 2 + 1]) { best[ma * 2 + 1] = c[ma][na][2]; bidx[ma * 2 + 1] = cb; }
                if (c[ma][na][3] > best[ma * 2 + 1]) { best[ma * 2 + 1] = c[ma][na][3]; bidx[ma * 2 + 1] = cb + 1; }
            }
        }
    }

    __syncthreads();
#pragma unroll
    for (int s = 0; s < 4; s++) {
        float v = best[s]; int ix = bidx[s];
#pragma unroll
        for (int off = 1; off <= 2; off <<= 1) {
            float ov = __shfl_xor_sync(0xffffffff, v, off);
            int   oi = __shfl_xor_sync(0xffffffff, ix, off);
            if (ov > v || (ov == v && oi < ix)) { v = ov; ix = oi; }
        }
        if (tig == 0) {
            int row = wm * 32 + (s >> 1) * 16 + gId + ((s & 1) ? 8 : 0);
            sval[row * 2 + wn] = v;
            sidx[row * 2 + wn] = ix;
        }
    }
    __syncthreads();
    if (tid < 128) {
        float bv = sval[tid * 2]; int bi = sidx[tid * 2];
        float v2 = sval[tid * 2 + 1]; int i2 = sidx[tid * 2 + 1];
        if (v2 > bv || (v2 == bv && i2 < bi)) { bv = v2; bi = i2; }
        g_pval[input][qseg][rb * 128 + tid] = bv;
        g_pidx[input][qseg][rb * 128 + tid] = bi;
    }
}

// ---------------- K3: EXACT fp32 rescore of segment candidates + gather ----------------
__global__ void k_gather(const float* __restrict__ queue) {
    int gw   = (blockIdx.x * blockDim.x + threadIdx.x) >> 5;
    int lane = threadIdx.x & 31;
    if (gw >= 2 * BSZ) return;
    int input = gw >> 12, row = gw & (BSZ - 1);
    float4 p = ((const float4*)(g_pn[input] + (size_t)row * DIM))[lane];
    float bv = -3.4e38f; int bi = 0x7fffffff;
#pragma unroll
    for (int s = 0; s < QSPLIT; s++) {
        int idx = g_pidx[input][s][row];
        float4 q = ((const float4*)(queue + (size_t)idx * DIM))[lane];
        float d = p.x * q.x + p.y * q.y + p.z * q.z + p.w * q.w;
#pragma unroll
        for (int o = 16; o; o >>= 1) d += __shfl_xor_sync(0xffffffff, d, o);
        if (d > bv || (d == bv && idx < bi)) { bv = d; bi = idx; }
    }
    float4 q = ((const float4*)(queue + (size_t)bi * DIM))[lane];
    ((float4*)(g_nn[input] + (size_t)row * DIM))[lane] = q;
}

// ---------------- K4: logits via 3xTF32 + fixed-shift exp partial sums ----------------
// grid (32, 2, 4), block 256. Each block: 128 rows x 1024 cols of matrix m.
#define LG_SMEM_BYTES ((A_FLOATS + BREGION_FLOATS + 64 + 256) * 4)   // ~104 KB

__global__ void __launch_bounds__(256, 2) k_logits() {
    extern __shared__ float smL[];
    float* As    = smL;
    float* Bbase = smL + A_FLOATS;
    float* scol  = Bbase + BREGION_FLOATS;     // [64]
    float* srow  = scol + 64;                  // [128][2]

    const int rb = blockIdx.x, m = blockIdx.y, nseg = blockIdx.z;
    const float* A  = g_nn[m] + (size_t)rb * 128 * DIM;
    const float* Bm = g_pn[1 - m];
    const int rowbase = nseg * NSEG_COLS;
    const int tid = threadIdx.x, lane = tid & 31, wid = tid >> 5;
    const int wm = wid & 3, wn = wid >> 2;
    const int gId = lane >> 2, tig = lane & 3;

#pragma unroll
    for (int x = 0; x < 16; x++) {
        int f = tid + x * 256;
        int row = f >> 5, kq = f & 31;
        float4 v = *(const float4*)(A + (size_t)row * DIM + kq * 4);
        *(float4*)(As + row * ASTRIDE + kq * 4) = v;
    }
    if (tid < 64) scol[tid] = 0.f;

    float rs[4];
#pragma unroll
    for (int s = 0; s < 4; s++) rs[s] = 0.f;

    const int NCH = (NSEG_COLS / 64) * 4;      // 64 chunks
    float4 pv[2];
    LOADB(Bm, rowbase, 0, pv);
    STOREB(Bbase, 0, pv);
    __syncthreads();

#pragma unroll 1
    for (int nt = 0; nt < NSEG_COLS / 64; nt++) {
        float c[2][4][4];
#pragma unroll
        for (int ma = 0; ma < 2; ma++)
#pragma unroll
            for (int na = 0; na < 4; na++)
#pragma unroll
                for (int r = 0; r < 4; r++) c[ma][na][r] = 0.f;

#pragma unroll 1
        for (int kk = 0; kk < 4; kk++) {
            int ch = nt * 4 + kk;
            if (ch + 1 < NCH) LOADB(Bm, rowbase, ch + 1, pv);
            MMA_CHUNK(As, Bbase, ch, c);
            if (ch + 1 < NCH) STOREB(Bbase, ch + 1, pv);
            __syncthreads();
        }

        // epilogue: l = c*10; e = exp(l-10); accumulate row + col partials
        float ctmp[4][2];
#pragma unroll
        for (int na = 0; na < 4; na++) { ctmp[na][0] = 0.f; ctmp[na][1] = 0.f; }
        int gcol0 = rowbase + nt * 64 + wn * 32;
#pragma unroll
        for (int ma = 0; ma < 2; ma++) {
#pragma unroll
            for (int na = 0; na < 4; na++) {
#pragma unroll
                for (int r = 0; r < 4; r++) {
                    float l = c[ma][na][r] * INV_T;
                    float e = __expf(l - SHIFT);
                    int half = r >> 1;
                    rs[ma * 2 + half] += e;
                    ctmp[na][r & 1] += e;
                    int grow = rb * 128 + wm * 32 + ma * 16 + gId + half * 8;
                    int gcol = gcol0 + na * 8 + 2 * tig + (r & 1);
                    if (gcol == grow) g_diag[m][grow] = l;
                }
            }
        }
        // reduce col partials over gId lanes (offsets 4,8,16)
#pragma unroll
        for (int na = 0; na < 4; na++)
#pragma unroll
            for (int r = 0; r < 2; r++) {
#pragma unroll
                for (int off = 4; off <= 16; off <<= 1)
                    ctmp[na][r] += __shfl_xor_sync(0xffffffff, ctmp[na][r], off);
            }
        if (gId == 0) {
#pragma unroll
            for (int na = 0; na < 4; na++) {
                atomicAdd(&scol[wn * 32 + na * 8 + 2 * tig + 0], ctmp[na][0]);
                atomicAdd(&scol[wn * 32 + na * 8 + 2 * tig + 1], ctmp[na][1]);
            }
        }
        __syncthreads();
        if (tid < 64) {
            g_colpart[m][rb][rowbase + nt * 64 + tid] = scol[tid];
            scol[tid] = 0.f;
        }
        // next tile's first chunk sync orders this reset before next atomics
    }

    // row partial sums: reduce over tig, then over the 2 wn warps via smem
#pragma unroll
    for (int s = 0; s < 4; s++) {
#pragma unroll
        for (int off = 1; off <= 2; off <<= 1)
            rs[s] += __shfl_xor_sync(0xffffffff, rs[s], off);
        if (tig == 0) {
            int rloc = wm * 32 + (s >> 1) * 16 + gId + ((s & 1) ? 8 : 0);
            srow[rloc * 2 + wn] = rs[s];
        }
    }
    __syncthreads();
    if (tid < 128)
        g_rowpart[m][nseg][rb * 128 + tid] = srow[tid * 2] + srow[tid * 2 + 1];
}

// ---------------- K5: final losses from partials ----------------
__global__ void k_loss(float* __restrict__ out) {
    int g = blockIdx.x * blockDim.x + threadIdx.x;
    if (g >= 2 * BSZ) return;
    int m = g >> 12, i = g & (BSZ - 1);
    float rsum = 0.f, csum = 0.f;
#pragma unroll
    for (int s = 0; s < NSEG; s++) rsum += g_rowpart[m][s][i];
#pragma unroll 8
    for (int rb = 0; rb < 32; rb++) csum += g_colpart[m][rb][i];
    float d = g_diag[m][i];
    out[(size_t)(2 * m) * BSZ + i]     = SHIFT + logf(rsum) - d;
    out[(size_t)(2 * m + 1) * BSZ + i] = SHIFT + logf(csum) - d;
}

// ---------------- launch ----------------
extern "C" void kernel_launch(void* const* d_in, const int* in_sizes, int n_in,
                              void* d_out, int out_size) {
    const float *p1 = nullptr, *p2 = nullptr, *queue = nullptr;
    for (int i = 0; i < n_in; i++) {
        if (in_sizes[i] == QSZ * DIM) queue = (const float*)d_in[i];
        else if (!p1) p1 = (const float*)d_in[i];
        else p2 = (const float*)d_in[i];
    }
    float* out = (float*)d_out;

    cudaFuncSetAttribute(k_nn, cudaFuncAttributeMaxDynamicSharedMemorySize, NN_SMEM_BYTES);
    cudaFuncSetAttribute(k_logits, cudaFuncAttributeMaxDynamicSharedMemorySize, LG_SMEM_BYTES);

    k_normalize<<<(2 * BSZ * 32 + 255) / 256, 256>>>(p1, p2);

    dim3 g2(BSZ / 128, 2, QSPLIT);
    k_nn<<<g2, 256, NN_SMEM_BYTES>>>(queue);

    k_gather<<<(2 * BSZ * 32 + 255) / 256, 256>>>(queue);

    dim3 g4(BSZ / 128, 2, NSEG);
    k_logits<<<g4, 256, LG_SMEM_BYTES>>>();

    k_loss<<<(2 * BSZ + 255) / 256, 256>>>(out);
}

// round 10
// speedup vs baseline: 1.1926x; 1.0204x over previous
#include <cuda_runtime.h>
#include <math.h>
#include <stdint.h>

#define BSZ   4096
#define QSZ   32768
#define DIM   128
#define QSPLIT 2
#define QPART (QSZ / QSPLIT)   // 16384
#define NSEG  4
#define NSEG_COLS (BSZ / NSEG) // 1024

#define INV_T 10.0f
#define SHIFT 10.0f

// ---------------- scratch (static device globals; no allocation) ----------------
__device__ float g_pn [2][BSZ * DIM];
__device__ float g_pnb[2][BSZ * DIM];
__device__ float g_pnr[2][BSZ * DIM];
__device__ float g_nn [2][BSZ * DIM];
__device__ float g_qb [QSZ * DIM];
__device__ float g_qr [QSZ * DIM];
__device__ float g_pval[2][QSPLIT][BSZ];
__device__ int   g_pidx[2][QSPLIT][BSZ];
__device__ float g_rowpart[2][NSEG][BSZ];
__device__ float g_colpart[2][32][BSZ];
__device__ float g_diag[2][BSZ];

// ---------------- helpers ----------------
__device__ __forceinline__ uint32_t smem_u32(const void* p) {
    uint32_t a;
    asm("{ .reg .u64 t; cvta.to.shared.u64 t, %1; cvt.u32.u64 %0, t; }" : "=r"(a) : "l"(p));
    return a;
}
__device__ __forceinline__ uint32_t to_tf32_rna(float x) {
    uint32_t r;
    asm("cvt.rna.tf32.f32 %0, %1;" : "=r"(r) : "f"(x));
    return r;
}
__device__ __forceinline__ void mma_tf32(float c[4], const uint32_t a[4], const uint32_t b[2]) {
    asm volatile(
        "mma.sync.aligned.m16n8k8.row.col.f32.tf32.tf32.f32 "
        "{%0,%1,%2,%3}, {%4,%5,%6,%7}, {%8,%9}, {%0,%1,%2,%3};\n"
        : "+f"(c[0]), "+f"(c[1]), "+f"(c[2]), "+f"(c[3])
        : "r"(a[0]), "r"(a[1]), "r"(a[2]), "r"(a[3]), "r"(b[0]), "r"(b[1]));
}
__device__ __forceinline__ void cp16(uint32_t dst, const void* src) {
    asm volatile("cp.async.cg.shared.global [%0], [%1], 16;" :: "r"(dst), "l"(src) : "memory");
}
#define CP_COMMIT() asm volatile("cp.async.commit_group;" ::: "memory")
#define CP_WAIT(n)  asm volatile("cp.async.wait_group %0;" :: "n"(n) : "memory")

// ---------------- K0: split queue into big/res ----------------
__global__ void k_qsplit(const float* __restrict__ queue) {
    int i = blockIdx.x * blockDim.x + threadIdx.x;
    if (i >= QSZ * DIM / 4) return;
    float4 v = ((const float4*)queue)[i];
    float4 bg, rr;
    bg.x = __uint_as_float(to_tf32_rna(v.x)); rr.x = v.x - bg.x;
    bg.y = __uint_as_float(to_tf32_rna(v.y)); rr.y = v.y - bg.y;
    bg.z = __uint_as_float(to_tf32_rna(v.z)); rr.z = v.z - bg.z;
    bg.w = __uint_as_float(to_tf32_rna(v.w)); rr.w = v.w - bg.w;
    ((float4*)g_qb)[i] = bg;
    ((float4*)g_qr)[i] = rr;
}

// ---------------- K1: L2 normalize + split ----------------
__global__ void k_normalize(const float* __restrict__ p1, const float* __restrict__ p2) {
    int gw   = (blockIdx.x * blockDim.x + threadIdx.x) >> 5;
    int lane = threadIdx.x & 31;
    if (gw >= 2 * BSZ) return;
    int input = gw >> 12;
    int row   = gw & (BSZ - 1);
    const float* src = (input ? p2 : p1) + (size_t)row * DIM;
    float4 v = ((const float4*)src)[lane];
    float s = v.x * v.x + v.y * v.y + v.z * v.z + v.w * v.w;
#pragma unroll
    for (int o = 16; o; o >>= 1) s += __shfl_xor_sync(0xffffffff, s, o);
    float inv = rsqrtf(s);
    float4 o4 = make_float4(v.x * inv, v.y * inv, v.z * inv, v.w * inv);
    ((float4*)(g_pn[input] + (size_t)row * DIM))[lane] = o4;
    float4 bg, rr;
    bg.x = __uint_as_float(to_tf32_rna(o4.x)); rr.x = o4.x - bg.x;
    bg.y = __uint_as_float(to_tf32_rna(o4.y)); rr.y = o4.y - bg.y;
    bg.z = __uint_as_float(to_tf32_rna(o4.z)); rr.z = o4.z - bg.z;
    bg.w = __uint_as_float(to_tf32_rna(o4.w)); rr.w = o4.w - bg.w;
    ((float4*)(g_pnb[input] + (size_t)row * DIM))[lane] = bg;
    ((float4*)(g_pnr[input] + (size_t)row * DIM))[lane] = rr;
}

// ---------------- K2: 3xTF32 mma GEMM + running argmax ----------------
// grid (32, 2, 2), block 256 (2 wm x 4 wn warps), warp tile 64x64.
// BM=128, BN=256, BK=32. A raw fp32 persistent in smem (split on the fly).
// B: pre-split g_qb/g_qr copied via cp.async, double-buffered [256][36] x2 arrays.
#define ASTRIDE 132
#define A_FLOATS (128 * ASTRIDE)              // 16896
#define BN_NN    256
#define BBUFN    (BN_NN * 36)                 // 9216 floats per array
#define BPAIR    (2 * BBUFN)                  // big+res for one buffer
#define NN_SMEM_FLOATS (A_FLOATS + 2 * BPAIR + 512 + 512)
#define NN_SMEM_BYTES  (NN_SMEM_FLOATS * 4)   // 219,136 B

__global__ void __launch_bounds__(256, 1) k_nn() {
    extern __shared__ float sm[];
    float* As    = sm;                         // [128][132]
    float* Bbase = sm + A_FLOATS;              // buf j: big @ j*BPAIR, res @ +BBUFN
    float* sval  = Bbase + 2 * BPAIR;          // [128][4]
    int*   sidx  = (int*)(sval + 512);         // [128][4]
    uint32_t sb_B = smem_u32(Bbase);

    const int rb = blockIdx.x, input = blockIdx.y, qseg = blockIdx.z;
    const float* A = g_pn[input] + (size_t)rb * 128 * DIM;
    const int tid = threadIdx.x, lane = tid & 31, wid = tid >> 5;
    const int wm = wid & 1, wn = wid >> 1;     // 2 x 4 warp grid
    const int gId = lane >> 2, tig = lane & 3;
    const size_t qbase = (size_t)qseg * QPART * DIM;

    // persistent raw A
#pragma unroll
    for (int x = 0; x < 16; x++) {
        int f = tid + x * 256;
        int row = f >> 5, kq = f & 31;
        float4 v = *(const float4*)(A + (size_t)row * DIM + kq * 4);
        *(float4*)(As + row * ASTRIDE + kq * 4) = v;
    }

    float best[8]; int bidx[8];
#pragma unroll
    for (int s = 0; s < 8; s++) { best[s] = -3.4e38f; bidx[s] = 0; }

    const int NCH = (QPART / BN_NN) * 4;       // 256 chunks (qt 64 x kk 4)

    // cp.async copy of chunk c into buffer c&1 (both arrays), 16 ops/thread
#define NN_COPY(c)                                                              \
    {                                                                           \
        int _qt = (c) >> 2, _kl = ((c) & 3) * 32;                               \
        uint32_t _db = sb_B + (uint32_t)(((c) & 1) * BPAIR) * 4;                \
        uint32_t _dr = _db + BBUFN * 4;                                         \
        _Pragma("unroll")                                                       \
        for (int _x = 0; _x < 8; _x++) {                                        \
            int _f = tid + _x * 256;                                            \
            int _row = _f >> 3, _kq = _f & 7;                                   \
            size_t _so = qbase + (size_t)(_qt * BN_NN + _row) * DIM + _kl + _kq * 4; \
            uint32_t _do_ = (uint32_t)(_row * 36 + _kq * 4) * 4;                \
            cp16(_db + _do_, g_qb + _so);                                       \
            cp16(_dr + _do_, g_qr + _so);                                       \
        }                                                                       \
    }

    NN_COPY(0);
    CP_COMMIT();

#pragma unroll 1
    for (int qt = 0; qt < QPART / BN_NN; qt++) {
        float c[4][8][4];
#pragma unroll
        for (int ma = 0; ma < 4; ma++)
#pragma unroll
            for (int na = 0; na < 8; na++)
#pragma unroll
                for (int r = 0; r < 4; r++) c[ma][na][r] = 0.f;

#pragma unroll 1
        for (int kk = 0; kk < 4; kk++) {
            int ch = qt * 4 + kk;
            if (ch + 1 < NCH) { NN_COPY(ch + 1); CP_COMMIT(); CP_WAIT(1); }
            else              { CP_WAIT(0); }
            __syncthreads();

            float* bb = Bbase + (ch & 1) * BPAIR;
            float* br = bb + BBUFN;
#pragma unroll
            for (int ka = 0; ka < 4; ka++) {
                int kglob = kk * 32 + ka * 8;
                uint32_t afb[4][4], afr[4][4], bfb[8][2], bfr[8][2];
#pragma unroll
                for (int ma = 0; ma < 4; ma++) {
                    int r0 = wm * 64 + ma * 16;
#pragma unroll
                    for (int q = 0; q < 4; q++) {
                        int rr2 = r0 + gId + ((q & 1) ? 8 : 0);
                        int ck  = kglob + tig + ((q & 2) ? 4 : 0);
                        float a = As[rr2 * ASTRIDE + ck];
                        uint32_t big = to_tf32_rna(a);
                        afb[ma][q] = big;
                        afr[ma][q] = __float_as_uint(a - __uint_as_float(big));
                    }
                }
#pragma unroll
                for (int na = 0; na < 8; na++) {
                    int base = (wn * 64 + na * 8 + gId) * 36 + ka * 8 + tig;
                    bfb[na][0] = __float_as_uint(bb[base]);
                    bfb[na][1] = __float_as_uint(bb[base + 4]);
                    bfr[na][0] = __float_as_uint(br[base]);
                    bfr[na][1] = __float_as_uint(br[base + 4]);
                }
                // term-reordered: all bb, then br, then rb
#pragma unroll
                for (int ma = 0; ma < 4; ma++)
#pragma unroll
                    for (int na = 0; na < 8; na++)
                        mma_tf32(c[ma][na], afb[ma], bfb[na]);
#pragma unroll
                for (int ma = 0; ma < 4; ma++)
#pragma unroll
                    for (int na = 0; na < 8; na++)
                        mma_tf32(c[ma][na], afb[ma], bfr[na]);
#pragma unroll
                for (int ma = 0; ma < 4; ma++)
#pragma unroll
                    for (int na = 0; na < 8; na++)
                        mma_tf32(c[ma][na], afr[ma], bfb[na]);
            }
            __syncthreads();
        }

        // fold this 256-col tile into running argmax
        int colb = qseg * QPART + qt * BN_NN + wn * 64;
#pragma unroll
        for (int ma = 0; ma < 4; ma++) {
#pragma unroll
            for (int na = 0; na < 8; na++) {
                int cb = colb + na * 8 + 2 * tig;
#pragma unroll
                for (int r = 0; r < 4; r++) {
                    int slot = ma * 2 + (r >> 1);
                    float v = c[ma][na][r];
                    if (v > best[slot]) { best[slot] = v; bidx[slot] = cb + (r & 1); }
                }
            }
        }
    }

    // reduce across tig lanes, then across the 4 column-warps
    __syncthreads();
#pragma unroll
    for (int s = 0; s < 8; s++) {
        float v = best[s]; int ix = bidx[s];
#pragma unroll
        for (int off = 1; off <= 2; off <<= 1) {
            float ov = __shfl_xor_sync(0xffffffff, v, off);
            int   oi = __shfl_xor_sync(0xffffffff, ix, off);
            if (ov > v || (ov == v && oi < ix)) { v = ov; ix = oi; }
        }
        if (tig == 0) {
            int row = wm * 64 + (s >> 1) * 16 + gId + ((s & 1) ? 8 : 0);
            sval[row * 4 + wn] = v;
            sidx[row * 4 + wn] = ix;
        }
    }
    __syncthreads();
    if (tid < 128) {
        float bv = -3.4e38f; int bi = 0x7fffffff;
#pragma unroll
        for (int w = 0; w < 4; w++) {
            float v = sval[tid * 4 + w]; int ix = sidx[tid * 4 + w];
            if (v > bv || (v == bv && ix < bi)) { bv = v; bi = ix; }
        }
        g_pval[input][qseg][rb * 128 + tid] = bv;
        g_pidx[input][qseg][rb * 128 + tid] = bi;
    }
}

// ---------------- K3: EXACT fp32 rescore of segment candidates + gather ----------------
__global__ void k_gather(const float* __restrict__ queue) {
    int gw   = (blockIdx.x * blockDim.x + threadIdx.x) >> 5;
    int lane = threadIdx.x & 31;
    if (gw >= 2 * BSZ) return;
    int input = gw >> 12, row = gw & (BSZ - 1);
    float4 p = ((const float4*)(g_pn[input] + (size_t)row * DIM))[lane];
    float bv = -3.4e38f; int bi = 0x7fffffff;
#pragma unroll
    for (int s = 0; s < QSPLIT; s++) {
        int idx = g_pidx[input][s][row];
        float4 q = ((const float4*)(queue + (size_t)idx * DIM))[lane];
        float d = p.x * q.x + p.y * q.y + p.z * q.z + p.w * q.w;
#pragma unroll
        for (int o = 16; o; o >>= 1) d += __shfl_xor_sync(0xffffffff, d, o);
        if (d > bv || (d == bv && idx < bi)) { bv = d; bi = idx; }
    }
    float4 q = ((const float4*)(queue + (size_t)bi * DIM))[lane];
    ((float4*)(g_nn[input] + (size_t)row * DIM))[lane] = q;
}

// ---------------- mma.sync engine macros for k_logits (pre-split B) ----------------
#define BSTRIDE 36
#define BBUF_FLOATS (64 * BSTRIDE)
#define BREGION_FLOATS (4 * BBUF_FLOATS)

#define LOADB2(Bb, Br, rowbase, ch, pvb, pvr)                                     \
    {                                                                             \
        int _qtn = (rowbase) + ((ch) >> 2) * 64, _kkn = ((ch) & 3) * 32;          \
        _Pragma("unroll")                                                         \
        for (int _x = 0; _x < 2; _x++) {                                          \
            int _f = tid + _x * 256, _row = _f >> 3, _kq = _f & 7;                \
            size_t _o = (size_t)(_qtn + _row) * DIM + _kkn + _kq * 4;             \
            pvb[_x] = *(const float4*)((Bb) + _o);                                \
            pvr[_x] = *(const float4*)((Br) + _o);                                \
        }                                                                         \
    }

#define STOREB2(Bbase, ch, pvb, pvr)                                              \
    {                                                                             \
        float* _bb = (Bbase) + ((ch) & 1) * (2 * BBUF_FLOATS);                    \
        float* _br = _bb + BBUF_FLOATS;                                           \
        _Pragma("unroll")                                                         \
        for (int _x = 0; _x < 2; _x++) {                                          \
            int _f = tid + _x * 256, _row = _f >> 3, _kq = _f & 7;                \
            *(float4*)(_bb + _row * BSTRIDE + _kq * 4) = pvb[_x];                 \
            *(float4*)(_br + _row * BSTRIDE + _kq * 4) = pvr[_x];                 \
        }                                                                         \
    }

#define MMA_CHUNK2(As, Bbase, ch, c)                                              \
    {                                                                             \
        float* _bb = (Bbase) + ((ch) & 1) * (2 * BBUF_FLOATS);                    \
        float* _br = _bb + BBUF_FLOATS;                                           \
        int _kkb = ((ch) & 3) * 32;                                               \
        _Pragma("unroll")                                                         \
        for (int _ka = 0; _ka < 4; _ka++) {                                       \
            int _k0 = _kkb + _ka * 8;                                             \
            uint32_t _afb[2][4], _afr[2][4], _bfb[4][2], _bfr[4][2];              \
            _Pragma("unroll")                                                     \
            for (int _ma = 0; _ma < 2; _ma++) {                                   \
                int _r0 = wm * 32 + _ma * 16;                                     \
                _Pragma("unroll")                                                 \
                for (int _q = 0; _q < 4; _q++) {                                  \
                    int _rr2 = _r0 + gId + ((_q & 1) ? 8 : 0);                    \
                    int _ck = _k0 + tig + ((_q & 2) ? 4 : 0);                     \
                    float _a = (As)[_rr2 * ASTRIDE + _ck];                        \
                    uint32_t _big = to_tf32_rna(_a);                              \
                    _afb[_ma][_q] = _big;                                         \
                    _afr[_ma][_q] = __float_as_uint(_a - __uint_as_float(_big));  \
                }                                                                 \
            }                                                                     \
            _Pragma("unroll")                                                     \
            for (int _na = 0; _na < 4; _na++) {                                   \
                int _base = (wn * 32 + _na * 8 + gId) * BSTRIDE + (_k0 - _kkb) + tig; \
                _bfb[_na][0] = __float_as_uint(_bb[_base]);                       \
                _bfb[_na][1] = __float_as_uint(_bb[_base + 4]);                   \
                _bfr[_na][0] = __float_as_uint(_br[_base]);                       \
                _bfr[_na][1] = __float_as_uint(_br[_base + 4]);                   \
            }                                                                     \
            _Pragma("unroll")                                                     \
            for (int _ma = 0; _ma < 2; _ma++)                                     \
                _Pragma("unroll")                                                 \
                for (int _na = 0; _na < 4; _na++)                                 \
                    mma_tf32(c[_ma][_na], _afb[_ma], _bfb[_na]);                  \
            _Pragma("unroll")                                                     \
            for (int _ma = 0; _ma < 2; _ma++)                                     \
                _Pragma("unroll")                                                 \
                for (int _na = 0; _na < 4; _na++)                                 \
                    mma_tf32(c[_ma][_na], _afb[_ma], _bfr[_na]);                  \
            _Pragma("unroll")                                                     \
            for (int _ma = 0; _ma < 2; _ma++)                                     \
                _Pragma("unroll")                                                 \
                for (int _na = 0; _na < 4; _na++)                                 \
                    mma_tf32(c[_ma][_na], _afr[_ma], _bfb[_na]);                  \
        }                                                                         \
    }

// ---------------- K4: logits via mma.sync 3xTF32 + fixed-shift exp partial sums ----------------
#define LG_SMEM_BYTES ((A_FLOATS + BREGION_FLOATS + 64 + 256) * 4)

__global__ void __launch_bounds__(256, 2) k_logits() {
    extern __shared__ float smL[];
    float* As    = smL;
    float* Bbase = smL + A_FLOATS;
    float* scol  = Bbase + BREGION_FLOATS;     // [64]
    float* srow  = scol + 64;                  // [128][2]

    const int rb = blockIdx.x, m = blockIdx.y, nseg = blockIdx.z;
    const float* A  = g_nn[m] + (size_t)rb * 128 * DIM;
    const float* Bb = g_pnb[1 - m];
    const float* Br = g_pnr[1 - m];
    const int rowbase = nseg * NSEG_COLS;
    const int tid = threadIdx.x, lane = tid & 31, wid = tid >> 5;
    const int wm = wid & 3, wn = wid >> 2;
    const int gId = lane >> 2, tig = lane & 3;

#pragma unroll
    for (int x = 0; x < 16; x++) {
        int f = tid + x * 256;
        int row = f >> 5, kq = f & 31;
        float4 v = *(const float4*)(A + (size_t)row * DIM + kq * 4);
        *(float4*)(As + row * ASTRIDE + kq * 4) = v;
    }
    if (tid < 64) scol[tid] = 0.f;

    float rs[4];
#pragma unroll
    for (int s = 0; s < 4; s++) rs[s] = 0.f;

    const int LNCH = (NSEG_COLS / 64) * 4;     // 64 chunks
    float4 pvb[2], pvr[2];
    LOADB2(Bb, Br, rowbase, 0, pvb, pvr);
    STOREB2(Bbase, 0, pvb, pvr);
    __syncthreads();

#pragma unroll 1
    for (int nt = 0; nt < NSEG_COLS / 64; nt++) {
        float c[2][4][4];
#pragma unroll
        for (int ma = 0; ma < 2; ma++)
#pragma unroll
            for (int na = 0; na < 4; na++)
#pragma unroll
                for (int r = 0; r < 4; r++) c[ma][na][r] = 0.f;

#pragma unroll 1
        for (int kk = 0; kk < 4; kk++) {
            int ch = nt * 4 + kk;
            if (ch + 1 < LNCH) LOADB2(Bb, Br, rowbase, ch + 1, pvb, pvr);
            MMA_CHUNK2(As, Bbase, ch, c);
            if (ch + 1 < LNCH) STOREB2(Bbase, ch + 1, pvb, pvr);
            __syncthreads();
        }

        float ctmp[4][2];
#pragma unroll
        for (int na = 0; na < 4; na++) { ctmp[na][0] = 0.f; ctmp[na][1] = 0.f; }
        int gcol0 = rowbase + nt * 64 + wn * 32;
#pragma unroll
        for (int ma = 0; ma < 2; ma++) {
#pragma unroll
            for (int na = 0; na < 4; na++) {
#pragma unroll
                for (int r = 0; r < 4; r++) {
                    float l = c[ma][na][r] * INV_T;
                    float e = __expf(l - SHIFT);
                    int half = r >> 1;
                    rs[ma * 2 + half] += e;
                    ctmp[na][r & 1] += e;
                    int grow = rb * 128 + wm * 32 + ma * 16 + gId + half * 8;
                    int gcol = gcol0 + na * 8 + 2 * tig + (r & 1);
                    if (gcol == grow) g_diag[m][grow] = l;
                }
            }
        }
#pragma unroll
        for (int na = 0; na < 4; na++)
#pragma unroll
            for (int r = 0; r < 2; r++) {
#pragma unroll
                for (int off = 4; off <= 16; off <<= 1)
                    ctmp[na][r] += __shfl_xor_sync(0xffffffff, ctmp[na][r], off);
            }
        if (gId == 0) {
#pragma unroll
            for (int na = 0; na < 4; na++) {
                atomicAdd(&scol[wn * 32 + na * 8 + 2 * tig + 0], ctmp[na][0]);
                atomicAdd(&scol[wn * 32 + na * 8 + 2 * tig + 1], ctmp[na][1]);
            }
        }
        __syncthreads();
        if (tid < 64) {
            g_colpart[m][rb][rowbase + nt * 64 + tid] = scol[tid];
            scol[tid] = 0.f;
        }
    }

#pragma unroll
    for (int s = 0; s < 4; s++) {
#pragma unroll
        for (int off = 1; off <= 2; off <<= 1)
            rs[s] += __shfl_xor_sync(0xffffffff, rs[s], off);
        if (tig == 0) {
            int rloc = wm * 32 + (s >> 1) * 16 + gId + ((s & 1) ? 8 : 0);
            srow[rloc * 2 + wn] = rs[s];
        }
    }
    __syncthreads();
    if (tid < 128)
        g_rowpart[m][nseg][rb * 128 + tid] = srow[tid * 2] + srow[tid * 2 + 1];
}

// ---------------- K5: final losses from partials ----------------
__global__ void k_loss(float* __restrict__ out) {
    int g = blockIdx.x * blockDim.x + threadIdx.x;
    if (g >= 2 * BSZ) return;
    int m = g >> 12, i = g & (BSZ - 1);
    float rsum = 0.f, csum = 0.f;
#pragma unroll
    for (int s = 0; s < NSEG; s++) rsum += g_rowpart[m][s][i];
#pragma unroll 8
    for (int rb = 0; rb < 32; rb++) csum += g_colpart[m][rb][i];
    float d = g_diag[m][i];
    out[(size_t)(2 * m) * BSZ + i]     = SHIFT + logf(rsum) - d;
    out[(size_t)(2 * m + 1) * BSZ + i] = SHIFT + logf(csum) - d;
}

// ---------------- launch ----------------
extern "C" void kernel_launch(void* const* d_in, const int* in_sizes, int n_in,
                              void* d_out, int out_size) {
    const float *p1 = nullptr, *p2 = nullptr, *queue = nullptr;
    for (int i = 0; i < n_in; i++) {
        if (in_sizes[i] == QSZ * DIM) queue = (const float*)d_in[i];
        else if (!p1) p1 = (const float*)d_in[i];
        else p2 = (const float*)d_in[i];
    }
    float* out = (float*)d_out;

    cudaFuncSetAttribute(k_nn, cudaFuncAttributeMaxDynamicSharedMemorySize, NN_SMEM_BYTES);
    cudaFuncSetAttribute(k_logits, cudaFuncAttributeMaxDynamicSharedMemorySize, LG_SMEM_BYTES);

    k_normalize<<<(2 * BSZ * 32 + 255) / 256, 256>>>(p1, p2);
    k_qsplit<<<(QSZ * DIM / 4 + 255) / 256, 256>>>(queue);

    dim3 g2(BSZ / 128, 2, QSPLIT);
    k_nn<<<g2, 256, NN_SMEM_BYTES>>>();

    k_gather<<<(2 * BSZ * 32 + 255) / 256, 256>>>(queue);

    dim3 g4(BSZ / 128, 2, NSEG);
    k_logits<<<g4, 256, LG_SMEM_BYTES>>>();

    k_loss<<<(2 * BSZ + 255) / 256, 256>>>(out);
}